// round 15
// baseline (speedup 1.0000x reference)
#include <cuda_runtime.h>
#include <cuda_fp16.h>
#include <math_constants.h>
#include <mma.h>
#include <cstdint>

using namespace nvcuda;

#define N_SRC  4096
#define N_DST  16384
#define C_IN   256
#define C_SKIP 128
#define C_CAT  384
#define HID    512

// scratch (no dynamic alloc allowed)
__device__ __half  g_hh[N_DST * C_CAT];   // h hi (fp16)
__device__ __half  g_hl[N_DST * C_CAT];   // h lo (fp16)
__device__ __half  g_dh[N_DST * HID];     // hidden hi
__device__ __half  g_dl[N_DST * HID];     // hidden lo
__device__ __half  g_w1[HID * C_CAT];     // W1^T fp16 [512][384]
__device__ __half  g_w2[C_CAT * HID];     // W2^T fp16 [384][512]

#define KNN_SMEM (N_SRC * 16 + 32 * 3 * 4 + 32 * 4 * 4)

// ======================== KNN (arithmetic LOCKED, passes 1.3e-7) ============
// 256 threads = 32 dst x 8 scan lanes; 512 blocks; 3 CTAs/SM resident.
__global__ __launch_bounds__(256) void knn_kernel(
    const float* __restrict__ x, const float* __restrict__ pos,
    const int* __restrict__ batch,
    const float* __restrict__ x_skip, const float* __restrict__ pos_skip,
    const int* __restrict__ batch_skip,
    __half* __restrict__ hh_out, __half* __restrict__ hl_out)
{
    extern __shared__ char smem_raw[];
    float4* sp   = (float4*)smem_raw;
    int*    s_id = (int*)  (smem_raw + N_SRC * 16);
    float*  s_w  = (float*)(smem_raw + N_SRC * 16 + 32 * 3 * 4);

    const int tid = threadIdx.x;

    for (int j = tid; j < N_SRC; j += 256) {
        float off = (float)batch[j] * 1000.0f;
        float p0 = __fadd_rn(pos[3 * j + 0], off);
        float p1 = __fadd_rn(pos[3 * j + 1], off);
        float p2 = __fadd_rn(pos[3 * j + 2], off);
        float pp = __fadd_rn(__fadd_rn(__fmul_rn(p0, p0), __fmul_rn(p1, p1)),
                             __fmul_rn(p2, p2));
        sp[j] = make_float4(2.0f * p0, 2.0f * p1, 2.0f * p2, pp);
    }
    __syncthreads();

    const int dl = tid >> 3;          // 0..31 local dst
    const int s  = tid & 7;           // scan lane
    const int d  = blockIdx.x * 32 + dl;

    float off = (float)batch_skip[d] * 1000.0f;
    float q0 = __fadd_rn(pos_skip[3 * d + 0], off);
    float q1 = __fadd_rn(pos_skip[3 * d + 1], off);
    float q2 = __fadd_rn(pos_skip[3 * d + 2], off);
    // qq: (0,2)-first SIMD hreduce pairing (LOCKED)
    float qq = __fadd_rn(__fadd_rn(__fmul_rn(q0, q0), __fmul_rn(q2, q2)),
                         __fmul_rn(q1, q1));

    float da = CUDART_INF_F, db = CUDART_INF_F, dc = CUDART_INF_F;
    int   ia = 0x7fffffff,  ib = 0x7fffffff,  ic = 0x7fffffff;

    #pragma unroll 4
    for (int j = s; j < N_SRC; j += 8) {
        float4 v = sp[j];
        float dot2 = __fmaf_rn(q2, v.z, __fmaf_rn(q1, v.y, __fmul_rn(q0, v.x)));
        float d2   = __fsub_rn(__fadd_rn(qq, v.w), dot2);
        if (d2 < dc) {
            if (d2 < db) {
                dc = db; ic = ib;
                if (d2 < da) { db = da; ib = ia; da = d2; ia = j; }
                else         { db = d2; ib = j; }
            } else { dc = d2; ic = j; }
        }
    }

    // Merge the 8 scan lanes (lexicographic (d2, idx) for ties).
    #pragma unroll
    for (int m = 1; m <= 4; m <<= 1) {
        float oa = __shfl_xor_sync(0xffffffff, da, m);
        float ob = __shfl_xor_sync(0xffffffff, db, m);
        float oc = __shfl_xor_sync(0xffffffff, dc, m);
        int   ja = __shfl_xor_sync(0xffffffff, ia, m);
        int   jb = __shfl_xor_sync(0xffffffff, ib, m);
        int   jc = __shfl_xor_sync(0xffffffff, ic, m);
        auto ins = [&](float dv, int iv) {
            bool ltc = (dv < dc) || (dv == dc && iv < ic);
            if (ltc) {
                bool ltb = (dv < db) || (dv == db && iv < ib);
                if (ltb) {
                    dc = db; ic = ib;
                    bool lta = (dv < da) || (dv == da && iv < ia);
                    if (lta) { db = da; ib = ia; da = dv; ia = iv; }
                    else     { db = dv; ib = iv; }
                } else { dc = dv; ic = iv; }
            }
        };
        ins(oa, ja); ins(ob, jb); ins(oc, jc);
    }

    if (s == 0) {
        float w0 = __fdiv_rn(1.0f, fmaxf(da, 1e-16f));
        float w1 = __fdiv_rn(1.0f, fmaxf(db, 1e-16f));
        float w2 = __fdiv_rn(1.0f, fmaxf(dc, 1e-16f));
        s_id[dl * 3 + 0] = ia; s_id[dl * 3 + 1] = ib; s_id[dl * 3 + 2] = ic;
        s_w[dl * 4 + 0] = w0; s_w[dl * 4 + 1] = w1; s_w[dl * 4 + 2] = w2;
        s_w[dl * 4 + 3] = __fadd_rn(__fadd_rn(w0, w1), w2);
    }
    __syncthreads();

    const int base = blockIdx.x * 32;
    #pragma unroll 2
    for (int t = 0; t < 32; t++) {
        int   i0 = s_id[t * 3 + 0], i1 = s_id[t * 3 + 1], i2 = s_id[t * 3 + 2];
        float w0 = s_w[t * 4 + 0],  w1 = s_w[t * 4 + 1],  w2 = s_w[t * 4 + 2];
        float sw = s_w[t * 4 + 3];
        int c = tid;
        float y0 = __fmul_rn(w0, x[i0 * C_IN + c]);
        float y1 = __fmul_rn(w1, x[i1 * C_IN + c]);
        float y2 = __fmul_rn(w2, x[i2 * C_IN + c]);
        float y  = __fadd_rn(__fadd_rn(y0, y1), y2);
        float val = __fdiv_rn(y, sw);
        size_t o = (size_t)(base + t) * C_CAT + c;
        __half vh = __float2half(val);
        hh_out[o] = vh;
        hl_out[o] = __float2half(val - __half2float(vh));
    }
    for (int idx = tid; idx < 32 * C_SKIP; idx += 256) {
        int t = idx >> 7, cs = idx & 127;
        float val = x_skip[(base + t) * C_SKIP + cs];
        size_t o = (size_t)(base + t) * C_CAT + C_IN + cs;
        __half vh = __float2half(val);
        hh_out[o] = vh;
        hl_out[o] = __float2half(val - __half2float(vh));
    }
}

// ============== weight transpose to fp16 (tiny prep) ========================
__global__ void convw_kernel(const float* __restrict__ W1,
                             const float* __restrict__ W2,
                             __half* __restrict__ w1t,
                             __half* __restrict__ w2t)
{
    int i = blockIdx.x * 256 + threadIdx.x;
    if (i < C_CAT * HID) {             // W1 [384,512] -> w1t [512,384]
        int k = i / HID, n = i % HID;
        w1t[n * C_CAT + k] = __float2half(W1[i]);
    }
    if (i < HID * C_CAT) {             // W2 [512,384] -> w2t [384,512]
        int k = i / C_CAT, n = i % C_CAT;
        w2t[n * HID + k] = __float2half(W2[i]);
    }
}

// ========= WMMA fp16 2-term GEMM, cp.async double-buffered ==================
// C[M,N] = (Ah+Al)[M,K] @ B^T[N,K], fp32 accum, 2 fp16 MMAs per frag.
// CTA 128x128, 8 warps (4M x 2N). K chunks of 64, 2 smem stages.
#define LDS2 72                           // smem row stride in halves (64+8)
#define OP_H (128 * LDS2)                 // halves per operand per stage
#define STAGE_H (3 * OP_H)                // halves per stage (Ah, Al, B)
#define G_SMEM (2 * STAGE_H * 2)          // 110592 bytes

__device__ __forceinline__ void cp16(uint32_t s, const void* g) {
    asm volatile("cp.async.cg.shared.global [%0], [%1], 16;"
                 :: "r"(s), "l"(g));
}

template <int KT, int NT, bool RELU, bool SPLIT>
__global__ __launch_bounds__(256, 2) void gemm_kernel(
    const __half* __restrict__ Ah, const __half* __restrict__ Al,
    const __half* __restrict__ B,
    const float* __restrict__ bias,
    const __half* __restrict__ resh, const __half* __restrict__ resl,
    __half* __restrict__ Oh, __half* __restrict__ Ol,
    float* __restrict__ Of)
{
    extern __shared__ char smem[];
    __half* sm = (__half*)smem;
    const uint32_t smem_b = (uint32_t)__cvta_generic_to_shared(smem);

    const int tid = threadIdx.x;
    const int wid = tid >> 5;
    const int n0 = blockIdx.x * 128;
    const int m0 = blockIdx.y * 128;
    const int wm = (wid & 3) * 32;
    const int wn = (wid >> 2) * 64;

    const __half* gsrc[3] = {
        Ah + (size_t)m0 * KT, Al + (size_t)m0 * KT, B + (size_t)n0 * KT };

    // one chunk = 64 k-halves: 3 operands x 128 rows x 128B = 3072 cp16
    auto prefetch = [&](int c, int st) {
        const int k0 = c * 64;
        const uint32_t sbase = smem_b + st * (STAGE_H * 2);
        #pragma unroll
        for (int i = tid; i < 3072; i += 256) {
            const int op = i >> 10, piece = i & 1023;
            const int r = piece >> 3, j = piece & 7;
            cp16(sbase + op * (OP_H * 2) + r * (LDS2 * 2) + j * 16,
                 (const char*)(gsrc[op] + (size_t)r * KT + k0) + j * 16);
        }
        asm volatile("cp.async.commit_group;" ::: "memory");
    };

    wmma::fragment<wmma::accumulator, 16, 16, 16, float> acc[2][4];
    #pragma unroll
    for (int i = 0; i < 2; i++)
        #pragma unroll
        for (int j = 0; j < 4; j++)
            wmma::fill_fragment(acc[i][j], 0.0f);

    constexpr int NCHUNK = KT / 64;
    prefetch(0, 0);
    prefetch(1, 1);

    for (int c = 0; c < NCHUNK; c++) {
        if (c + 2 <= NCHUNK - 1)
            asm volatile("cp.async.wait_group 1;" ::: "memory");
        else
            asm volatile("cp.async.wait_group 0;" ::: "memory");
        __syncthreads();

        const __half* sAh = sm + (c & 1) * STAGE_H;
        const __half* sAl = sAh + OP_H;
        const __half* sB  = sAl + OP_H;

        #pragma unroll
        for (int ks = 0; ks < 4; ks++) {
            const int kk = ks * 16;
            wmma::fragment<wmma::matrix_a, 16, 16, 16, __half,
                           wmma::row_major> a_h[2], a_l[2];
            #pragma unroll
            for (int i = 0; i < 2; i++) {
                wmma::load_matrix_sync(a_h[i], sAh + (wm + i * 16) * LDS2 + kk, LDS2);
                wmma::load_matrix_sync(a_l[i], sAl + (wm + i * 16) * LDS2 + kk, LDS2);
            }
            #pragma unroll
            for (int j = 0; j < 4; j++) {
                wmma::fragment<wmma::matrix_b, 16, 16, 16, __half,
                               wmma::col_major> b;
                wmma::load_matrix_sync(b, sB + (wn + j * 16) * LDS2 + kk, LDS2);
                #pragma unroll
                for (int i = 0; i < 2; i++) {
                    wmma::mma_sync(acc[i][j], a_h[i], b, acc[i][j]);
                    wmma::mma_sync(acc[i][j], a_l[i], b, acc[i][j]);
                }
            }
        }
        __syncthreads();
        if (c + 2 < NCHUNK) prefetch(c + 2, c & 1);
    }

    // epilogue: stage fp32 tile through smem (reuse operand space, 64KB)
    float* sC = (float*)smem;
    #pragma unroll
    for (int i = 0; i < 2; i++)
        #pragma unroll
        for (int j = 0; j < 4; j++)
            wmma::store_matrix_sync(sC + (wm + i * 16) * 128 + wn + j * 16,
                                    acc[i][j], 128, wmma::mem_row_major);
    __syncthreads();

    for (int idx = tid; idx < 128 * 128; idx += 256) {
        const int r = idx >> 7, cc = idx & 127;
        const int m = m0 + r, n = n0 + cc;
        float v = sC[idx] + bias[n];
        if (RELU) v = fmaxf(v, 0.0f);
        if (SPLIT) {
            __half vh = __float2half(v);
            Oh[(size_t)m * NT + n] = vh;
            Ol[(size_t)m * NT + n] = __float2half(v - __half2float(vh));
        } else {
            // residual reconstructed from fp16 hi/lo split (err ~2^-22)
            float rres = __half2float(resh[(size_t)m * NT + n]) +
                         __half2float(resl[(size_t)m * NT + n]);
            Of[(size_t)m * NT + n] = v + rres;
        }
    }
}

// ======================== tail outputs ======================================
__global__ void tail_kernel(const float* __restrict__ pos_skip,
                            const int* __restrict__ batch_skip,
                            float* __restrict__ out, int write_batch)
{
    int i = blockIdx.x * 256 + threadIdx.x;
    if (i < N_DST * 3) out[N_DST * C_CAT + i] = pos_skip[i];
    if (write_batch && i < N_DST)
        out[N_DST * C_CAT + N_DST * 3 + i] = (float)batch_skip[i];
}

extern "C" void kernel_launch(void* const* d_in, const int* in_sizes, int n_in,
                              void* d_out, int out_size)
{
    const float* x          = (const float*)d_in[0];
    const float* pos        = (const float*)d_in[1];
    const int*   batch      = (const int*)d_in[2];
    const float* x_skip     = (const float*)d_in[3];
    const float* pos_skip   = (const float*)d_in[4];
    const int*   batch_skip = (const int*)d_in[5];
    const float* W1         = (const float*)d_in[6];
    const float* b1         = (const float*)d_in[7];
    const float* W2         = (const float*)d_in[8];
    const float* b2         = (const float*)d_in[9];
    float* out = (float*)d_out;

    __half *hh, *hl, *dh, *dl, *w1t, *w2t;
    cudaGetSymbolAddress((void**)&hh, g_hh);
    cudaGetSymbolAddress((void**)&hl, g_hl);
    cudaGetSymbolAddress((void**)&dh, g_dh);
    cudaGetSymbolAddress((void**)&dl, g_dl);
    cudaGetSymbolAddress((void**)&w1t, g_w1);
    cudaGetSymbolAddress((void**)&w2t, g_w2);

    cudaFuncSetAttribute(knn_kernel,
                         cudaFuncAttributeMaxDynamicSharedMemorySize, KNN_SMEM);
    cudaFuncSetAttribute(gemm_kernel<C_CAT, HID, true, true>,
                         cudaFuncAttributeMaxDynamicSharedMemorySize, G_SMEM);
    cudaFuncSetAttribute(gemm_kernel<HID, C_CAT, false, false>,
                         cudaFuncAttributeMaxDynamicSharedMemorySize, G_SMEM);

    convw_kernel<<<(C_CAT * HID + 255) / 256, 256>>>(W1, W2, w1t, w2t);

    knn_kernel<<<N_DST / 32, 256, KNN_SMEM>>>(x, pos, batch, x_skip, pos_skip,
                                              batch_skip, hh, hl);

    // hidden = relu(h @ W1 + b1)  -> fp16 split
    gemm_kernel<C_CAT, HID, true, true>
        <<<dim3(HID / 128, N_DST / 128), 256, G_SMEM>>>(
            hh, hl, w1t, b1, nullptr, nullptr, dh, dl, nullptr);

    // out = hidden @ W2 + b2 + (hh + hl)
    gemm_kernel<HID, C_CAT, false, false>
        <<<dim3(C_CAT / 128, N_DST / 128), 256, G_SMEM>>>(
            dh, dl, w2t, b2, hh, hl, nullptr, nullptr, out);

    if (out_size >= N_DST * C_CAT + N_DST * 3) {
        int wb = (out_size >= N_DST * C_CAT + N_DST * 3 + N_DST) ? 1 : 0;
        tail_kernel<<<(N_DST * 3 + 255) / 256, 256>>>(pos_skip, batch_skip,
                                                      out, wb);
    }
}

// round 16
// speedup vs baseline: 1.3191x; 1.3191x over previous
#include <cuda_runtime.h>
#include <cuda_fp16.h>
#include <math_constants.h>
#include <mma.h>
#include <cstdint>

using namespace nvcuda;

#define N_SRC  4096
#define N_DST  16384
#define C_IN   256
#define C_SKIP 128
#define C_CAT  384
#define HID    512

// scratch (no dynamic alloc allowed)
__device__ __half  g_hh[N_DST * C_CAT];   // h hi (fp16)
__device__ __half  g_hl[N_DST * C_CAT];   // h lo (fp16, residual reconstruction)
__device__ __half  g_dh[N_DST * HID];     // hidden (fp16)
__device__ __half  g_w1[HID * C_CAT];     // W1^T fp16 [512][384]
__device__ __half  g_w2[C_CAT * HID];     // W2^T fp16 [384][512]

#define KNN_SMEM (N_SRC * 16 + 64 * 3 * 4 + 64 * 4 * 4)

// ======================== KNN (arithmetic LOCKED, passes 1.3e-7) ============
// R13-proven config: 256 threads = 64 dst x 4 scan lanes, 256 blocks.
__global__ __launch_bounds__(256) void knn_kernel(
    const float* __restrict__ x, const float* __restrict__ pos,
    const int* __restrict__ batch,
    const float* __restrict__ x_skip, const float* __restrict__ pos_skip,
    const int* __restrict__ batch_skip,
    __half* __restrict__ hh_out, __half* __restrict__ hl_out)
{
    extern __shared__ char smem_raw[];
    float4* sp   = (float4*)smem_raw;
    int*    s_id = (int*)  (smem_raw + N_SRC * 16);
    float*  s_w  = (float*)(smem_raw + N_SRC * 16 + 64 * 3 * 4);

    const int tid = threadIdx.x;

    for (int j = tid; j < N_SRC; j += 256) {
        float off = (float)batch[j] * 1000.0f;
        float p0 = __fadd_rn(pos[3 * j + 0], off);
        float p1 = __fadd_rn(pos[3 * j + 1], off);
        float p2 = __fadd_rn(pos[3 * j + 2], off);
        float pp = __fadd_rn(__fadd_rn(__fmul_rn(p0, p0), __fmul_rn(p1, p1)),
                             __fmul_rn(p2, p2));
        sp[j] = make_float4(2.0f * p0, 2.0f * p1, 2.0f * p2, pp);
    }
    __syncthreads();

    const int dl = tid >> 2;          // 0..63 local dst
    const int s  = tid & 3;           // scan lane
    const int d  = blockIdx.x * 64 + dl;

    float off = (float)batch_skip[d] * 1000.0f;
    float q0 = __fadd_rn(pos_skip[3 * d + 0], off);
    float q1 = __fadd_rn(pos_skip[3 * d + 1], off);
    float q2 = __fadd_rn(pos_skip[3 * d + 2], off);
    // qq: (0,2)-first SIMD hreduce pairing (LOCKED)
    float qq = __fadd_rn(__fadd_rn(__fmul_rn(q0, q0), __fmul_rn(q2, q2)),
                         __fmul_rn(q1, q1));

    float da = CUDART_INF_F, db = CUDART_INF_F, dc = CUDART_INF_F;
    int   ia = 0x7fffffff,  ib = 0x7fffffff,  ic = 0x7fffffff;

    #pragma unroll 4
    for (int j = s; j < N_SRC; j += 4) {
        float4 v = sp[j];
        float dot2 = __fmaf_rn(q2, v.z, __fmaf_rn(q1, v.y, __fmul_rn(q0, v.x)));
        float d2   = __fsub_rn(__fadd_rn(qq, v.w), dot2);
        if (d2 < dc) {
            if (d2 < db) {
                dc = db; ic = ib;
                if (d2 < da) { db = da; ib = ia; da = d2; ia = j; }
                else         { db = d2; ib = j; }
            } else { dc = d2; ic = j; }
        }
    }

    // Merge the 4 scan lanes (lexicographic (d2, idx) for ties).
    #pragma unroll
    for (int m = 1; m <= 2; m <<= 1) {
        float oa = __shfl_xor_sync(0xffffffff, da, m);
        float ob = __shfl_xor_sync(0xffffffff, db, m);
        float oc = __shfl_xor_sync(0xffffffff, dc, m);
        int   ja = __shfl_xor_sync(0xffffffff, ia, m);
        int   jb = __shfl_xor_sync(0xffffffff, ib, m);
        int   jc = __shfl_xor_sync(0xffffffff, ic, m);
        auto ins = [&](float dv, int iv) {
            bool ltc = (dv < dc) || (dv == dc && iv < ic);
            if (ltc) {
                bool ltb = (dv < db) || (dv == db && iv < ib);
                if (ltb) {
                    dc = db; ic = ib;
                    bool lta = (dv < da) || (dv == da && iv < ia);
                    if (lta) { db = da; ib = ia; da = dv; ia = iv; }
                    else     { db = dv; ib = iv; }
                } else { dc = dv; ic = iv; }
            }
        };
        ins(oa, ja); ins(ob, jb); ins(oc, jc);
    }

    if (s == 0) {
        float w0 = __fdiv_rn(1.0f, fmaxf(da, 1e-16f));
        float w1 = __fdiv_rn(1.0f, fmaxf(db, 1e-16f));
        float w2 = __fdiv_rn(1.0f, fmaxf(dc, 1e-16f));
        s_id[dl * 3 + 0] = ia; s_id[dl * 3 + 1] = ib; s_id[dl * 3 + 2] = ic;
        s_w[dl * 4 + 0] = w0; s_w[dl * 4 + 1] = w1; s_w[dl * 4 + 2] = w2;
        s_w[dl * 4 + 3] = __fadd_rn(__fadd_rn(w0, w1), w2);
    }
    __syncthreads();

    const int base = blockIdx.x * 64;
    #pragma unroll 2
    for (int t = 0; t < 64; t++) {
        int   i0 = s_id[t * 3 + 0], i1 = s_id[t * 3 + 1], i2 = s_id[t * 3 + 2];
        float w0 = s_w[t * 4 + 0],  w1 = s_w[t * 4 + 1],  w2 = s_w[t * 4 + 2];
        float sw = s_w[t * 4 + 3];
        int c = tid;
        float y0 = __fmul_rn(w0, x[i0 * C_IN + c]);
        float y1 = __fmul_rn(w1, x[i1 * C_IN + c]);
        float y2 = __fmul_rn(w2, x[i2 * C_IN + c]);
        float y  = __fadd_rn(__fadd_rn(y0, y1), y2);
        float val = __fdiv_rn(y, sw);
        size_t o = (size_t)(base + t) * C_CAT + c;
        __half vh = __float2half(val);
        hh_out[o] = vh;
        hl_out[o] = __float2half(val - __half2float(vh));
    }
    for (int idx = tid; idx < 64 * C_SKIP; idx += 256) {
        int t = idx >> 7, cs = idx & 127;
        float val = x_skip[(base + t) * C_SKIP + cs];
        size_t o = (size_t)(base + t) * C_CAT + C_IN + cs;
        __half vh = __float2half(val);
        hh_out[o] = vh;
        hl_out[o] = __float2half(val - __half2float(vh));
    }
}

// ============== weight transpose to fp16 (tiny prep) ========================
__global__ void convw_kernel(const float* __restrict__ W1,
                             const float* __restrict__ W2,
                             __half* __restrict__ w1t,
                             __half* __restrict__ w2t)
{
    int i = blockIdx.x * 256 + threadIdx.x;
    if (i < C_CAT * HID) {             // W1 [384,512] -> w1t [512,384]
        int k = i / HID, n = i % HID;
        w1t[n * C_CAT + k] = __float2half(W1[i]);
    }
    if (i < HID * C_CAT) {             // W2 [512,384] -> w2t [384,512]
        int k = i / C_CAT, n = i % C_CAT;
        w2t[n * HID + k] = __float2half(W2[i]);
    }
}

// ============ WMMA plain fp16 GEMM, cp.async double-buffered ================
// C[M,N] = A[M,K] @ B^T[N,K], fp32 accum, 1 fp16 MMA per frag.
// CTA 128x128, 8 warps (4M x 2N). K chunks of 32, 2 smem stages (R13 schedule).
#define LDS2 40                           // smem row stride in halves (32+8)
#define OP_H (128 * LDS2)                 // halves per operand per stage
#define STAGE_H (2 * OP_H)                // halves per stage (A, B)
#define G_SMEM 65536                      // max(2*STAGE_H*2=40960, epi 64KB)

__device__ __forceinline__ void cp16(uint32_t s, const void* g) {
    asm volatile("cp.async.cg.shared.global [%0], [%1], 16;"
                 :: "r"(s), "l"(g));
}

template <int KT, int NT, bool RELU, bool SPLIT>
__global__ __launch_bounds__(256, 2) void gemm_kernel(
    const __half* __restrict__ A, const __half* __restrict__ B,
    const float* __restrict__ bias,
    const __half* __restrict__ resh, const __half* __restrict__ resl,
    __half* __restrict__ Oh, float* __restrict__ Of)
{
    extern __shared__ char smem[];
    __half* sm = (__half*)smem;
    const uint32_t smem_b = (uint32_t)__cvta_generic_to_shared(smem);

    const int tid = threadIdx.x;
    const int wid = tid >> 5;
    const int n0 = blockIdx.x * 128;
    const int m0 = blockIdx.y * 128;
    const int wm = (wid & 3) * 32;
    const int wn = (wid >> 2) * 64;

    const __half* gsrc[2] = { A + (size_t)m0 * KT, B + (size_t)n0 * KT };

    // one chunk = 32 k-halves: 2 operands x 128 rows x 64B = 1024 cp16
    auto prefetch = [&](int c, int st) {
        const int k0 = c * 32;
        const uint32_t sbase = smem_b + st * (STAGE_H * 2);
        #pragma unroll
        for (int i = tid; i < 1024; i += 256) {
            const int op = i >> 9, piece = i & 511;
            const int r = piece >> 2, j = piece & 3;
            cp16(sbase + op * (OP_H * 2) + r * (LDS2 * 2) + j * 16,
                 (const char*)(gsrc[op] + (size_t)r * KT + k0) + j * 16);
        }
        asm volatile("cp.async.commit_group;" ::: "memory");
    };

    wmma::fragment<wmma::accumulator, 16, 16, 16, float> acc[2][4];
    #pragma unroll
    for (int i = 0; i < 2; i++)
        #pragma unroll
        for (int j = 0; j < 4; j++)
            wmma::fill_fragment(acc[i][j], 0.0f);

    constexpr int NCHUNK = KT / 32;
    prefetch(0, 0);
    prefetch(1, 1);

    for (int c = 0; c < NCHUNK; c++) {
        if (c + 2 <= NCHUNK - 1)
            asm volatile("cp.async.wait_group 1;" ::: "memory");
        else
            asm volatile("cp.async.wait_group 0;" ::: "memory");
        __syncthreads();

        const __half* sA = sm + (c & 1) * STAGE_H;
        const __half* sB = sA + OP_H;

        #pragma unroll
        for (int ks = 0; ks < 2; ks++) {
            const int kk = ks * 16;
            wmma::fragment<wmma::matrix_a, 16, 16, 16, __half,
                           wmma::row_major> a[2];
            #pragma unroll
            for (int i = 0; i < 2; i++)
                wmma::load_matrix_sync(a[i], sA + (wm + i * 16) * LDS2 + kk, LDS2);
            #pragma unroll
            for (int j = 0; j < 4; j++) {
                wmma::fragment<wmma::matrix_b, 16, 16, 16, __half,
                               wmma::col_major> b;
                wmma::load_matrix_sync(b, sB + (wn + j * 16) * LDS2 + kk, LDS2);
                #pragma unroll
                for (int i = 0; i < 2; i++)
                    wmma::mma_sync(acc[i][j], a[i], b, acc[i][j]);
            }
        }
        __syncthreads();
        if (c + 2 < NCHUNK) prefetch(c + 2, c & 1);
    }

    // epilogue: stage fp32 tile through smem (reuse operand space, 64KB)
    float* sC = (float*)smem;
    #pragma unroll
    for (int i = 0; i < 2; i++)
        #pragma unroll
        for (int j = 0; j < 4; j++)
            wmma::store_matrix_sync(sC + (wm + i * 16) * 128 + wn + j * 16,
                                    acc[i][j], 128, wmma::mem_row_major);
    __syncthreads();

    for (int idx = tid; idx < 128 * 128; idx += 256) {
        const int r = idx >> 7, cc = idx & 127;
        const int m = m0 + r, n = n0 + cc;
        float v = sC[idx] + bias[n];
        if (RELU) v = fmaxf(v, 0.0f);
        if (SPLIT) {
            Oh[(size_t)m * NT + n] = __float2half(v);
        } else {
            // residual reconstructed from fp16 hi/lo split (err ~2^-22)
            float rres = __half2float(resh[(size_t)m * NT + n]) +
                         __half2float(resl[(size_t)m * NT + n]);
            Of[(size_t)m * NT + n] = v + rres;
        }
    }
}

// ======================== tail outputs ======================================
__global__ void tail_kernel(const float* __restrict__ pos_skip,
                            const int* __restrict__ batch_skip,
                            float* __restrict__ out, int write_batch)
{
    int i = blockIdx.x * 256 + threadIdx.x;
    if (i < N_DST * 3) out[N_DST * C_CAT + i] = pos_skip[i];
    if (write_batch && i < N_DST)
        out[N_DST * C_CAT + N_DST * 3 + i] = (float)batch_skip[i];
}

extern "C" void kernel_launch(void* const* d_in, const int* in_sizes, int n_in,
                              void* d_out, int out_size)
{
    const float* x          = (const float*)d_in[0];
    const float* pos        = (const float*)d_in[1];
    const int*   batch      = (const int*)d_in[2];
    const float* x_skip     = (const float*)d_in[3];
    const float* pos_skip   = (const float*)d_in[4];
    const int*   batch_skip = (const int*)d_in[5];
    const float* W1         = (const float*)d_in[6];
    const float* b1         = (const float*)d_in[7];
    const float* W2         = (const float*)d_in[8];
    const float* b2         = (const float*)d_in[9];
    float* out = (float*)d_out;

    __half *hh, *hl, *dh, *w1t, *w2t;
    cudaGetSymbolAddress((void**)&hh, g_hh);
    cudaGetSymbolAddress((void**)&hl, g_hl);
    cudaGetSymbolAddress((void**)&dh, g_dh);
    cudaGetSymbolAddress((void**)&w1t, g_w1);
    cudaGetSymbolAddress((void**)&w2t, g_w2);

    cudaFuncSetAttribute(knn_kernel,
                         cudaFuncAttributeMaxDynamicSharedMemorySize, KNN_SMEM);
    cudaFuncSetAttribute(gemm_kernel<C_CAT, HID, true, true>,
                         cudaFuncAttributeMaxDynamicSharedMemorySize, G_SMEM);
    cudaFuncSetAttribute(gemm_kernel<HID, C_CAT, false, false>,
                         cudaFuncAttributeMaxDynamicSharedMemorySize, G_SMEM);

    convw_kernel<<<(C_CAT * HID + 255) / 256, 256>>>(W1, W2, w1t, w2t);

    knn_kernel<<<N_DST / 64, 256, KNN_SMEM>>>(x, pos, batch, x_skip, pos_skip,
                                              batch_skip, hh, hl);

    // hidden = relu(h @ W1 + b1)  -> fp16
    gemm_kernel<C_CAT, HID, true, true>
        <<<dim3(HID / 128, N_DST / 128), 256, G_SMEM>>>(
            hh, w1t, b1, nullptr, nullptr, dh, nullptr);

    // out = hidden @ W2 + b2 + (hh + hl)
    gemm_kernel<HID, C_CAT, false, false>
        <<<dim3(C_CAT / 128, N_DST / 128), 256, G_SMEM>>>(
            dh, w2t, b2, hh, hl, nullptr, out);

    if (out_size >= N_DST * C_CAT + N_DST * 3) {
        int wb = (out_size >= N_DST * C_CAT + N_DST * 3 + N_DST) ? 1 : 0;
        tail_kernel<<<(N_DST * 3 + 255) / 256, 256>>>(pos_skip, batch_skip,
                                                      out, wb);
    }
}

// round 17
// speedup vs baseline: 1.5475x; 1.1731x over previous
#include <cuda_runtime.h>
#include <cuda_fp16.h>
#include <math_constants.h>
#include <mma.h>
#include <cstdint>

using namespace nvcuda;

#define N_SRC  4096
#define N_DST  16384
#define C_IN   256
#define C_SKIP 128
#define C_CAT  384
#define HID    512

// scratch (no dynamic alloc allowed)
__device__ __half  g_hh[N_DST * C_CAT];   // h hi (fp16)
__device__ __half  g_hl[N_DST * C_CAT];   // h lo (fp16, residual reconstruction)
__device__ __half  g_dh[N_DST * HID];     // hidden (fp16)
__device__ __half  g_w1[HID * C_CAT];     // W1^T fp16 [512][384]
__device__ __half  g_w2[C_CAT * HID];     // W2^T fp16 [384][512]

#define KNN_SMEM (N_SRC * 16 + 64 * 3 * 4 + 64 * 4 * 4 + 16)

// ======================== KNN (arithmetic LOCKED, passes 1.3e-7) ============
// 256 threads = 64 dst x 4 scan lanes, 256 blocks.
// Scan restricted to own-batch index range: cross-batch d2 ~= 1e6 can never
// enter the top-3 (in-batch d2 ~= O(1)), so selection/weights are bit-identical.
__global__ __launch_bounds__(256) void knn_kernel(
    const float* __restrict__ x, const float* __restrict__ pos,
    const int* __restrict__ batch,
    const float* __restrict__ x_skip, const float* __restrict__ pos_skip,
    const int* __restrict__ batch_skip,
    __half* __restrict__ hh_out, __half* __restrict__ hl_out)
{
    extern __shared__ char smem_raw[];
    float4* sp   = (float4*)smem_raw;
    int*    s_id = (int*)  (smem_raw + N_SRC * 16);
    float*  s_w  = (float*)(smem_raw + N_SRC * 16 + 64 * 3 * 4);
    int*    s_n0 = (int*)  (smem_raw + N_SRC * 16 + 64 * 3 * 4 + 64 * 4 * 4);

    const int tid = threadIdx.x;

    if (tid == 0) {  // first index with batch >= 1 (batch sorted)
        int lo = 0, hi = N_SRC;
        while (lo < hi) { int mid = (lo + hi) >> 1;
                          if (batch[mid] < 1) lo = mid + 1; else hi = mid; }
        *s_n0 = lo;
    }

    for (int j = tid; j < N_SRC; j += 256) {
        float off = (float)batch[j] * 1000.0f;
        float p0 = __fadd_rn(pos[3 * j + 0], off);
        float p1 = __fadd_rn(pos[3 * j + 1], off);
        float p2 = __fadd_rn(pos[3 * j + 2], off);
        float pp = __fadd_rn(__fadd_rn(__fmul_rn(p0, p0), __fmul_rn(p1, p1)),
                             __fmul_rn(p2, p2));
        sp[j] = make_float4(2.0f * p0, 2.0f * p1, 2.0f * p2, pp);
    }
    __syncthreads();

    const int dl = tid >> 2;          // 0..63 local dst
    const int s  = tid & 3;           // scan lane
    const int d  = blockIdx.x * 64 + dl;
    const int nb0 = *s_n0;

    const int bq = batch_skip[d];
    int jlo = bq ? nb0 : 0;
    int jhi = bq ? N_SRC : nb0;
    if (jhi - jlo < 4) { jlo = 0; jhi = N_SRC; }  // degenerate-range fallback

    float off = (float)bq * 1000.0f;
    float q0 = __fadd_rn(pos_skip[3 * d + 0], off);
    float q1 = __fadd_rn(pos_skip[3 * d + 1], off);
    float q2 = __fadd_rn(pos_skip[3 * d + 2], off);
    // qq: (0,2)-first SIMD hreduce pairing (LOCKED)
    float qq = __fadd_rn(__fadd_rn(__fmul_rn(q0, q0), __fmul_rn(q2, q2)),
                         __fmul_rn(q1, q1));

    float da = CUDART_INF_F, db = CUDART_INF_F, dc = CUDART_INF_F;
    int   ia = 0x7fffffff,  ib = 0x7fffffff,  ic = 0x7fffffff;

    #pragma unroll 4
    for (int j = jlo + s; j < jhi; j += 4) {
        float4 v = sp[j];
        float dot2 = __fmaf_rn(q2, v.z, __fmaf_rn(q1, v.y, __fmul_rn(q0, v.x)));
        float d2   = __fsub_rn(__fadd_rn(qq, v.w), dot2);
        if (d2 < dc) {
            if (d2 < db) {
                dc = db; ic = ib;
                if (d2 < da) { db = da; ib = ia; da = d2; ia = j; }
                else         { db = d2; ib = j; }
            } else { dc = d2; ic = j; }
        }
    }

    // Merge the 4 scan lanes (lexicographic (d2, idx) for ties).
    #pragma unroll
    for (int m = 1; m <= 2; m <<= 1) {
        float oa = __shfl_xor_sync(0xffffffff, da, m);
        float ob = __shfl_xor_sync(0xffffffff, db, m);
        float oc = __shfl_xor_sync(0xffffffff, dc, m);
        int   ja = __shfl_xor_sync(0xffffffff, ia, m);
        int   jb = __shfl_xor_sync(0xffffffff, ib, m);
        int   jc = __shfl_xor_sync(0xffffffff, ic, m);
        auto ins = [&](float dv, int iv) {
            bool ltc = (dv < dc) || (dv == dc && iv < ic);
            if (ltc) {
                bool ltb = (dv < db) || (dv == db && iv < ib);
                if (ltb) {
                    dc = db; ic = ib;
                    bool lta = (dv < da) || (dv == da && iv < ia);
                    if (lta) { db = da; ib = ia; da = dv; ia = iv; }
                    else     { db = dv; ib = iv; }
                } else { dc = dv; ic = iv; }
            }
        };
        ins(oa, ja); ins(ob, jb); ins(oc, jc);
    }

    if (s == 0) {
        float w0 = __fdiv_rn(1.0f, fmaxf(da, 1e-16f));
        float w1 = __fdiv_rn(1.0f, fmaxf(db, 1e-16f));
        float w2 = __fdiv_rn(1.0f, fmaxf(dc, 1e-16f));
        s_id[dl * 3 + 0] = ia; s_id[dl * 3 + 1] = ib; s_id[dl * 3 + 2] = ic;
        s_w[dl * 4 + 0] = w0; s_w[dl * 4 + 1] = w1; s_w[dl * 4 + 2] = w2;
        s_w[dl * 4 + 3] = __fadd_rn(__fadd_rn(w0, w1), w2);
    }
    __syncthreads();

    const int base = blockIdx.x * 64;
    #pragma unroll 2
    for (int t = 0; t < 64; t++) {
        int   i0 = s_id[t * 3 + 0], i1 = s_id[t * 3 + 1], i2 = s_id[t * 3 + 2];
        float w0 = s_w[t * 4 + 0],  w1 = s_w[t * 4 + 1],  w2 = s_w[t * 4 + 2];
        float sw = s_w[t * 4 + 3];
        int c = tid;
        float y0 = __fmul_rn(w0, x[i0 * C_IN + c]);
        float y1 = __fmul_rn(w1, x[i1 * C_IN + c]);
        float y2 = __fmul_rn(w2, x[i2 * C_IN + c]);
        float y  = __fadd_rn(__fadd_rn(y0, y1), y2);
        float val = __fdiv_rn(y, sw);
        size_t o = (size_t)(base + t) * C_CAT + c;
        __half vh = __float2half(val);
        hh_out[o] = vh;
        hl_out[o] = __float2half(val - __half2float(vh));
    }
    for (int idx = tid; idx < 64 * C_SKIP; idx += 256) {
        int t = idx >> 7, cs = idx & 127;
        float val = x_skip[(base + t) * C_SKIP + cs];
        size_t o = (size_t)(base + t) * C_CAT + C_IN + cs;
        __half vh = __float2half(val);
        hh_out[o] = vh;
        hl_out[o] = __float2half(val - __half2float(vh));
    }
}

// ====== weight transpose to fp16 + tail outputs (fused prep kernel) =========
__global__ void convw_kernel(const float* __restrict__ W1,
                             const float* __restrict__ W2,
                             __half* __restrict__ w1t,
                             __half* __restrict__ w2t,
                             const float* __restrict__ pos_skip,
                             const int* __restrict__ batch_skip,
                             float* __restrict__ out, int tail_mode)
{
    int i = blockIdx.x * 256 + threadIdx.x;
    if (i < C_CAT * HID) {             // W1 [384,512] -> w1t [512,384]
        int k = i / HID, n = i % HID;
        w1t[n * C_CAT + k] = __float2half(W1[i]);
    }
    if (i < HID * C_CAT) {             // W2 [512,384] -> w2t [384,512]
        int k = i / C_CAT, n = i % C_CAT;
        w2t[n * HID + k] = __float2half(W2[i]);
    }
    if (tail_mode >= 1 && i < N_DST * 3)
        out[N_DST * C_CAT + i] = pos_skip[i];
    if (tail_mode >= 2 && i < N_DST)
        out[N_DST * C_CAT + N_DST * 3 + i] = (float)batch_skip[i];
}

// ============ WMMA plain fp16 GEMM, cp.async double-buffered ================
// C[M,N] = A[M,K] @ B^T[N,K], fp32 accum. CTA tile 128(M) x 64(N), 8 warps
// (4M x 2N), warp tile 32x32. K chunks of 32, 2 smem stages. 3 CTAs/SM.
#define LDS2 40                           // smem row stride in halves (32+8)
#define A_H (128 * LDS2)                  // A halves per stage
#define B_H (64 * LDS2)                   // B halves per stage
#define STAGE_H (A_H + B_H)
#define G_SMEM 32768                      // max(2*STAGE_H*2=30720, epi 32KB)

__device__ __forceinline__ void cp16(uint32_t s, const void* g) {
    asm volatile("cp.async.cg.shared.global [%0], [%1], 16;"
                 :: "r"(s), "l"(g));
}

template <int KT, int NT, bool RELU, bool SPLIT>
__global__ __launch_bounds__(256, 3) void gemm_kernel(
    const __half* __restrict__ A, const __half* __restrict__ B,
    const float* __restrict__ bias,
    const __half* __restrict__ resh, const __half* __restrict__ resl,
    __half* __restrict__ Oh, float* __restrict__ Of)
{
    extern __shared__ char smem[];
    __half* sm = (__half*)smem;
    const uint32_t smem_b = (uint32_t)__cvta_generic_to_shared(smem);

    const int tid = threadIdx.x;
    const int wid = tid >> 5;
    const int n0 = blockIdx.x * 64;
    const int m0 = blockIdx.y * 128;
    const int wm = (wid & 3) * 32;
    const int wn = (wid >> 2) * 32;

    const __half* gA = A + (size_t)m0 * KT;
    const __half* gB = B + (size_t)n0 * KT;

    // one chunk = 32 k-halves: (128 A rows + 64 B rows) x 64B = 768 cp16
    auto prefetch = [&](int c, int st) {
        const int k0 = c * 32;
        const uint32_t sbase = smem_b + st * (STAGE_H * 2);
        #pragma unroll
        for (int i = tid; i < 768; i += 256) {
            const int r = i >> 2, j = i & 3;      // r: 0..127 A, 128..191 B
            const __half* g = (r < 128) ? gA + (size_t)r * KT + k0
                                        : gB + (size_t)(r - 128) * KT + k0;
            cp16(sbase + r * (LDS2 * 2) + j * 16, (const char*)g + j * 16);
        }
        asm volatile("cp.async.commit_group;" ::: "memory");
    };

    wmma::fragment<wmma::accumulator, 16, 16, 16, float> acc[2][2];
    #pragma unroll
    for (int i = 0; i < 2; i++)
        #pragma unroll
        for (int j = 0; j < 2; j++)
            wmma::fill_fragment(acc[i][j], 0.0f);

    constexpr int NCHUNK = KT / 32;
    prefetch(0, 0);
    prefetch(1, 1);

    for (int c = 0; c < NCHUNK; c++) {
        if (c + 2 <= NCHUNK - 1)
            asm volatile("cp.async.wait_group 1;" ::: "memory");
        else
            asm volatile("cp.async.wait_group 0;" ::: "memory");
        __syncthreads();

        const __half* sA = sm + (c & 1) * STAGE_H;
        const __half* sB = sA + A_H;

        #pragma unroll
        for (int ks = 0; ks < 2; ks++) {
            const int kk = ks * 16;
            wmma::fragment<wmma::matrix_a, 16, 16, 16, __half,
                           wmma::row_major> a[2];
            #pragma unroll
            for (int i = 0; i < 2; i++)
                wmma::load_matrix_sync(a[i], sA + (wm + i * 16) * LDS2 + kk, LDS2);
            #pragma unroll
            for (int j = 0; j < 2; j++) {
                wmma::fragment<wmma::matrix_b, 16, 16, 16, __half,
                               wmma::col_major> b;
                wmma::load_matrix_sync(b, sB + (wn + j * 16) * LDS2 + kk, LDS2);
                #pragma unroll
                for (int i = 0; i < 2; i++)
                    wmma::mma_sync(acc[i][j], a[i], b, acc[i][j]);
            }
        }
        __syncthreads();
        if (c + 2 < NCHUNK) prefetch(c + 2, c & 1);
    }

    // epilogue: stage fp32 tile (128x64) through smem
    float* sC = (float*)smem;
    #pragma unroll
    for (int i = 0; i < 2; i++)
        #pragma unroll
        for (int j = 0; j < 2; j++)
            wmma::store_matrix_sync(sC + (wm + i * 16) * 64 + wn + j * 16,
                                    acc[i][j], 64, wmma::mem_row_major);
    __syncthreads();

    for (int idx = tid; idx < 128 * 64; idx += 256) {
        const int r = idx >> 6, cc = idx & 63;
        const int m = m0 + r, n = n0 + cc;
        float v = sC[idx] + bias[n];
        if (RELU) v = fmaxf(v, 0.0f);
        if (SPLIT) {
            Oh[(size_t)m * NT + n] = __float2half(v);
        } else {
            // residual reconstructed from fp16 hi/lo split (err ~2^-22)
            float rres = __half2float(resh[(size_t)m * NT + n]) +
                         __half2float(resl[(size_t)m * NT + n]);
            Of[(size_t)m * NT + n] = v + rres;
        }
    }
}

extern "C" void kernel_launch(void* const* d_in, const int* in_sizes, int n_in,
                              void* d_out, int out_size)
{
    const float* x          = (const float*)d_in[0];
    const float* pos        = (const float*)d_in[1];
    const int*   batch      = (const int*)d_in[2];
    const float* x_skip     = (const float*)d_in[3];
    const float* pos_skip   = (const float*)d_in[4];
    const int*   batch_skip = (const int*)d_in[5];
    const float* W1         = (const float*)d_in[6];
    const float* b1         = (const float*)d_in[7];
    const float* W2         = (const float*)d_in[8];
    const float* b2         = (const float*)d_in[9];
    float* out = (float*)d_out;

    __half *hh, *hl, *dh, *w1t, *w2t;
    cudaGetSymbolAddress((void**)&hh, g_hh);
    cudaGetSymbolAddress((void**)&hl, g_hl);
    cudaGetSymbolAddress((void**)&dh, g_dh);
    cudaGetSymbolAddress((void**)&w1t, g_w1);
    cudaGetSymbolAddress((void**)&w2t, g_w2);

    cudaFuncSetAttribute(knn_kernel,
                         cudaFuncAttributeMaxDynamicSharedMemorySize, KNN_SMEM);
    cudaFuncSetAttribute(gemm_kernel<C_CAT, HID, true, true>,
                         cudaFuncAttributeMaxDynamicSharedMemorySize, G_SMEM);
    cudaFuncSetAttribute(gemm_kernel<HID, C_CAT, false, false>,
                         cudaFuncAttributeMaxDynamicSharedMemorySize, G_SMEM);

    int tail_mode = 0;
    if (out_size >= N_DST * C_CAT + N_DST * 3) tail_mode = 1;
    if (out_size >= N_DST * C_CAT + N_DST * 3 + N_DST) tail_mode = 2;

    convw_kernel<<<(C_CAT * HID + 255) / 256, 256>>>(
        W1, W2, w1t, w2t, pos_skip, batch_skip, out, tail_mode);

    knn_kernel<<<N_DST / 64, 256, KNN_SMEM>>>(x, pos, batch, x_skip, pos_skip,
                                              batch_skip, hh, hl);

    // hidden = relu(h @ W1 + b1)  -> fp16
    gemm_kernel<C_CAT, HID, true, true>
        <<<dim3(HID / 64, N_DST / 128), 256, G_SMEM>>>(
            hh, w1t, b1, nullptr, nullptr, dh, nullptr);

    // out = hidden @ W2 + b2 + (hh + hl)
    gemm_kernel<HID, C_CAT, false, false>
        <<<dim3(C_CAT / 64, N_DST / 128), 256, G_SMEM>>>(
            dh, w2t, b2, hh, hl, nullptr, out);
}